// round 4
// baseline (speedup 1.0000x reference)
#include <cuda_runtime.h>
#include <cuda_fp16.h>
#include <mma.h>

using namespace nvcuda;

// Problem dims
#define BATCH   2
#define SEQ     4096
#define DIN     512
#define DOUT    512
#define MTOT    (BATCH * SEQ)          // 8192 rows for projections
#define QSCALE  0.04419417382415922f   // 1/sqrt(512)

// GEMM tiling
#define BM 128
#define BN 128
#define BK 32
#define NTHREADS 256

// Scratch (device globals; no allocation in kernel_launch allowed)
__device__ __align__(128) __half g_Q[(size_t)MTOT * DOUT];
__device__ __align__(128) __half g_K[(size_t)MTOT * DOUT];
__device__ __align__(128) __half g_V[(size_t)MTOT * DOUT];
__device__ __align__(128) float  g_S[(size_t)BATCH * SEQ * SEQ];   // fp32 scores
__device__ __align__(128) __half g_P[(size_t)BATCH * SEQ * SEQ];   // fp16 softmax weights

// ---------------------------------------------------------------------------
// Kernel 1: fused projections  out[m,n] = sum_k x[m,k] * W[k,n]  (fp16 out)
// blockIdx.z: 0 -> Q (Wq), 1 -> K (Wk), 2 -> V (Wv)
// ---------------------------------------------------------------------------
__global__ void proj_kernel(const float* __restrict__ x,
                            const float* __restrict__ Wq,
                            const float* __restrict__ Wk,
                            const float* __restrict__ Wv) {
    const int which = blockIdx.z;
    const float* W = (which == 0) ? Wq : (which == 1) ? Wk : Wv;
    __half* outbuf = (which == 0) ? g_Q : (which == 1) ? g_K : g_V;

    __shared__ __half sA[BM][BK + 8];     // x tile (fp16)
    __shared__ __half sB[BK][BN + 8];     // W tile (fp16, row-major k x n)
    __shared__ float stage[8][16][20];    // per-warp fp32 staging

    const int m0 = blockIdx.y * BM;
    const int n0 = blockIdx.x * BN;
    const int tid = threadIdx.x;
    const int wid = tid >> 5;
    const int lane = tid & 31;
    const int wr = wid >> 2;   // 0..1  (64-row slabs)
    const int wc = wid & 3;    // 0..3  (32-col slabs)

    wmma::fragment<wmma::accumulator, 16, 16, 16, float> acc[4][2];
#pragma unroll
    for (int i = 0; i < 4; i++)
#pragma unroll
        for (int j = 0; j < 2; j++) wmma::fill_fragment(acc[i][j], 0.0f);

    for (int k0 = 0; k0 < DIN; k0 += BK) {
        // Load A tile: 128 x 32 fp32 -> fp16.  1024 float4 units.
#pragma unroll
        for (int it = 0; it < 4; it++) {
            int u = tid + it * NTHREADS;
            int r = u >> 3, g = u & 7;                 // 8 float4 per row
            float4 v = *(const float4*)&x[(size_t)(m0 + r) * DIN + k0 + g * 4];
            __half2 p0 = __floats2half2_rn(v.x, v.y);
            __half2 p1 = __floats2half2_rn(v.z, v.w);
            *(__half2*)&sA[r][g * 4]     = p0;
            *(__half2*)&sA[r][g * 4 + 2] = p1;
        }
        // Load B tile: 32 x 128 fp32 -> fp16. 1024 float4 units.
#pragma unroll
        for (int it = 0; it < 4; it++) {
            int u = tid + it * NTHREADS;
            int r = u >> 5, g = u & 31;                // 32 float4 per row
            float4 v = *(const float4*)&W[(size_t)(k0 + r) * DOUT + n0 + g * 4];
            __half2 p0 = __floats2half2_rn(v.x, v.y);
            __half2 p1 = __floats2half2_rn(v.z, v.w);
            *(__half2*)&sB[r][g * 4]     = p0;
            *(__half2*)&sB[r][g * 4 + 2] = p1;
        }
        __syncthreads();

#pragma unroll
        for (int kk = 0; kk < BK; kk += 16) {
            wmma::fragment<wmma::matrix_a, 16, 16, 16, __half, wmma::row_major> af[4];
            wmma::fragment<wmma::matrix_b, 16, 16, 16, __half, wmma::row_major> bf[2];
#pragma unroll
            for (int i = 0; i < 4; i++)
                wmma::load_matrix_sync(af[i], &sA[wr * 64 + i * 16][kk], BK + 8);
#pragma unroll
            for (int j = 0; j < 2; j++)
                wmma::load_matrix_sync(bf[j], &sB[kk][wc * 32 + j * 16], BN + 8);
#pragma unroll
            for (int i = 0; i < 4; i++)
#pragma unroll
                for (int j = 0; j < 2; j++)
                    wmma::mma_sync(acc[i][j], af[i], bf[j], acc[i][j]);
        }
        __syncthreads();
    }

    // Store via per-warp staging, convert to fp16.
#pragma unroll
    for (int i = 0; i < 4; i++) {
#pragma unroll
        for (int j = 0; j < 2; j++) {
            wmma::store_matrix_sync(&stage[wid][0][0], acc[i][j], 20, wmma::mem_row_major);
            __syncwarp();
#pragma unroll
            for (int q = 0; q < 8; q++) {
                int e = lane * 8 + q;
                int r = e >> 4, c = e & 15;
                size_t go = (size_t)(m0 + wr * 64 + i * 16 + r) * DOUT + (n0 + wc * 32 + j * 16 + c);
                outbuf[go] = __float2half(stage[wid][r][c]);
            }
            __syncwarp();
        }
    }
}

// ---------------------------------------------------------------------------
// Kernel 2: scores  S[b,m,n] = sum_d Q[b,m,d] * K[b,n,d]   (fp32 out, unscaled)
// ---------------------------------------------------------------------------
__global__ void scores_kernel() {
    const int b = blockIdx.z;
    const __half* Qb = g_Q + (size_t)b * SEQ * DOUT;
    const __half* Kb = g_K + (size_t)b * SEQ * DOUT;
    float* Sb = g_S + (size_t)b * SEQ * SEQ;

    __shared__ __half sA[BM][BK + 8];   // Q tile
    __shared__ __half sB[BN][BK + 8];   // K tile ([n][k] -> col_major B frag)

    const int m0 = blockIdx.y * BM;
    const int n0 = blockIdx.x * BN;
    const int tid = threadIdx.x;
    const int wid = tid >> 5;
    const int wr = wid >> 2;
    const int wc = wid & 3;

    wmma::fragment<wmma::accumulator, 16, 16, 16, float> acc[4][2];
#pragma unroll
    for (int i = 0; i < 4; i++)
#pragma unroll
        for (int j = 0; j < 2; j++) wmma::fill_fragment(acc[i][j], 0.0f);

    for (int k0 = 0; k0 < DOUT; k0 += BK) {
        // A: 128 x 32 fp16 = 512 uint4
#pragma unroll
        for (int it = 0; it < 2; it++) {
            int u = tid + it * NTHREADS;
            int r = u >> 2, g = u & 3;   // 4 uint4 per row
            *(uint4*)&sA[r][g * 8] = *(const uint4*)&Qb[(size_t)(m0 + r) * DOUT + k0 + g * 8];
        }
        // B: 128 x 32 fp16 (rows are K's n index)
#pragma unroll
        for (int it = 0; it < 2; it++) {
            int u = tid + it * NTHREADS;
            int r = u >> 2, g = u & 3;
            *(uint4*)&sB[r][g * 8] = *(const uint4*)&Kb[(size_t)(n0 + r) * DOUT + k0 + g * 8];
        }
        __syncthreads();

#pragma unroll
        for (int kk = 0; kk < BK; kk += 16) {
            wmma::fragment<wmma::matrix_a, 16, 16, 16, __half, wmma::row_major> af[4];
            wmma::fragment<wmma::matrix_b, 16, 16, 16, __half, wmma::col_major> bf[2];
#pragma unroll
            for (int i = 0; i < 4; i++)
                wmma::load_matrix_sync(af[i], &sA[wr * 64 + i * 16][kk], BK + 8);
#pragma unroll
            for (int j = 0; j < 2; j++)
                wmma::load_matrix_sync(bf[j], &sB[wc * 32 + j * 16][kk], BK + 8);
#pragma unroll
            for (int i = 0; i < 4; i++)
#pragma unroll
                for (int j = 0; j < 2; j++)
                    wmma::mma_sync(acc[i][j], af[i], bf[j], acc[i][j]);
        }
        __syncthreads();
    }

#pragma unroll
    for (int i = 0; i < 4; i++)
#pragma unroll
        for (int j = 0; j < 2; j++)
            wmma::store_matrix_sync(&Sb[(size_t)(m0 + wr * 64 + i * 16) * SEQ + n0 + wc * 32 + j * 16],
                                    acc[i][j], SEQ, wmma::mem_row_major);
}

// ---------------------------------------------------------------------------
// Kernel 3: row softmax with scale, fp32 in -> fp16 out.  One block per row.
// ---------------------------------------------------------------------------
__global__ void softmax_kernel() {
    const size_t row = blockIdx.x;                 // 0 .. BATCH*SEQ-1
    const float* s = g_S + row * SEQ;
    __half* p = g_P + row * SEQ;
    const int tid = threadIdx.x;
    const int wid = tid >> 5;
    const int lane = tid & 31;

    __shared__ float red[8];

    float4 v[4];
    float m = -1e30f;
#pragma unroll
    for (int i = 0; i < 4; i++) {
        v[i] = ((const float4*)s)[i * 256 + tid];
        m = fmaxf(m, fmaxf(fmaxf(v[i].x, v[i].y), fmaxf(v[i].z, v[i].w)));
    }
#pragma unroll
    for (int o = 16; o > 0; o >>= 1) m = fmaxf(m, __shfl_xor_sync(0xffffffffu, m, o));
    if (lane == 0) red[wid] = m;
    __syncthreads();
    float rowmax = red[0];
#pragma unroll
    for (int k = 1; k < 8; k++) rowmax = fmaxf(rowmax, red[k]);
    __syncthreads();

    float e[16];
    float sum = 0.0f;
#pragma unroll
    for (int i = 0; i < 4; i++) {
        e[i * 4 + 0] = __expf((v[i].x - rowmax) * QSCALE);
        e[i * 4 + 1] = __expf((v[i].y - rowmax) * QSCALE);
        e[i * 4 + 2] = __expf((v[i].z - rowmax) * QSCALE);
        e[i * 4 + 3] = __expf((v[i].w - rowmax) * QSCALE);
        sum += e[i * 4 + 0] + e[i * 4 + 1] + e[i * 4 + 2] + e[i * 4 + 3];
    }
#pragma unroll
    for (int o = 16; o > 0; o >>= 1) sum += __shfl_xor_sync(0xffffffffu, sum, o);
    if (lane == 0) red[wid] = sum;
    __syncthreads();
    float rowsum = 0.0f;
#pragma unroll
    for (int k = 0; k < 8; k++) rowsum += red[k];
    const float inv = 1.0f / rowsum;

#pragma unroll
    for (int i = 0; i < 4; i++) {
        __half2 p0 = __floats2half2_rn(e[i * 4 + 0] * inv, e[i * 4 + 1] * inv);
        __half2 p1 = __floats2half2_rn(e[i * 4 + 2] * inv, e[i * 4 + 3] * inv);
        size_t c = (size_t)(i * 256 + tid) * 4;
        *(__half2*)&p[c]     = p0;
        *(__half2*)&p[c + 2] = p1;
    }
}

// ---------------------------------------------------------------------------
// Kernel 4: output  O[b,m,d] = sum_k P[b,m,k] * V[b,k,d]   (fp32 out)
// ---------------------------------------------------------------------------
__global__ void out_kernel(float* __restrict__ out) {
    const int b = blockIdx.z;
    const __half* Pb = g_P + (size_t)b * SEQ * SEQ;
    const __half* Vb = g_V + (size_t)b * SEQ * DOUT;
    float* Ob = out + (size_t)b * SEQ * DOUT;

    __shared__ __half sA[BM][BK + 8];   // P tile
    __shared__ __half sB[BK][BN + 8];   // V tile (row-major k x n)

    const int m0 = blockIdx.y * BM;
    const int n0 = blockIdx.x * BN;
    const int tid = threadIdx.x;
    const int wid = tid >> 5;
    const int wr = wid >> 2;
    const int wc = wid & 3;

    wmma::fragment<wmma::accumulator, 16, 16, 16, float> acc[4][2];
#pragma unroll
    for (int i = 0; i < 4; i++)
#pragma unroll
        for (int j = 0; j < 2; j++) wmma::fill_fragment(acc[i][j], 0.0f);

    for (int k0 = 0; k0 < SEQ; k0 += BK) {
        // A: 128 x 32 fp16
#pragma unroll
        for (int it = 0; it < 2; it++) {
            int u = tid + it * NTHREADS;
            int r = u >> 2, g = u & 3;
            *(uint4*)&sA[r][g * 8] = *(const uint4*)&Pb[(size_t)(m0 + r) * SEQ + k0 + g * 8];
        }
        // B: 32 x 128 fp16
#pragma unroll
        for (int it = 0; it < 2; it++) {
            int u = tid + it * NTHREADS;
            int r = u >> 4, g = u & 15;   // 16 uint4 per row
            *(uint4*)&sB[r][g * 8] = *(const uint4*)&Vb[(size_t)(k0 + r) * DOUT + n0 + g * 8];
        }
        __syncthreads();

#pragma unroll
        for (int kk = 0; kk < BK; kk += 16) {
            wmma::fragment<wmma::matrix_a, 16, 16, 16, __half, wmma::row_major> af[4];
            wmma::fragment<wmma::matrix_b, 16, 16, 16, __half, wmma::row_major> bf[2];
#pragma unroll
            for (int i = 0; i < 4; i++)
                wmma::load_matrix_sync(af[i], &sA[wr * 64 + i * 16][kk], BK + 8);
#pragma unroll
            for (int j = 0; j < 2; j++)
                wmma::load_matrix_sync(bf[j], &sB[kk][wc * 32 + j * 16], BN + 8);
#pragma unroll
            for (int i = 0; i < 4; i++)
#pragma unroll
                for (int j = 0; j < 2; j++)
                    wmma::mma_sync(acc[i][j], af[i], bf[j], acc[i][j]);
        }
        __syncthreads();
    }

#pragma unroll
    for (int i = 0; i < 4; i++)
#pragma unroll
        for (int j = 0; j < 2; j++)
            wmma::store_matrix_sync(&Ob[(size_t)(m0 + wr * 64 + i * 16) * DOUT + n0 + wc * 32 + j * 16],
                                    acc[i][j], DOUT, wmma::mem_row_major);
}

// ---------------------------------------------------------------------------
extern "C" void kernel_launch(void* const* d_in, const int* in_sizes, int n_in,
                              void* d_out, int out_size) {
    const float* x  = (const float*)d_in[0];
    const float* Wq = (const float*)d_in[1];
    const float* Wk = (const float*)d_in[2];
    const float* Wv = (const float*)d_in[3];
    float* out = (float*)d_out;

    dim3 gproj(DOUT / BN, MTOT / BM, 3);           // (4, 64, 3)
    proj_kernel<<<gproj, NTHREADS>>>(x, Wq, Wk, Wv);

    dim3 gsc(SEQ / BN, SEQ / BM, BATCH);           // (32, 32, 2)
    scores_kernel<<<gsc, NTHREADS>>>();

    softmax_kernel<<<BATCH * SEQ, 256>>>();

    dim3 gout(DOUT / BN, SEQ / BM, BATCH);         // (4, 32, 2)
    out_kernel<<<gout, NTHREADS>>>(out);
}

// round 7
// speedup vs baseline: 1.1629x; 1.1629x over previous
#include <cuda_runtime.h>
#include <cuda_fp16.h>
#include <mma.h>

using namespace nvcuda;

// Problem dims
#define BATCH   2
#define SEQ     4096
#define DIN     512
#define DOUT    512
#define MTOT    (BATCH * SEQ)
#define QSCALE  0.04419417382415922f   // 1/sqrt(512)

// Projection GEMM tiling (proven R4 config)
#define BM 128
#define BN 128
#define BK 32
#define NTHREADS 256

// Big-GEMM tiling (scores / out): BK2 = 64, register-prefetch double buffer
#define BK2 64

// Scratch (device globals)
__device__ __align__(128) __half g_Q[(size_t)MTOT * DOUT];
__device__ __align__(128) __half g_K[(size_t)MTOT * DOUT];
__device__ __align__(128) __half g_V[(size_t)MTOT * DOUT];
__device__ __align__(128) float  g_S[(size_t)BATCH * SEQ * SEQ];
__device__ __align__(128) __half g_P[(size_t)BATCH * SEQ * SEQ];

// ---------------------------------------------------------------------------
// Kernel 1: fused projections (fp16 out)
// ---------------------------------------------------------------------------
__global__ void proj_kernel(const float* __restrict__ x,
                            const float* __restrict__ Wq,
                            const float* __restrict__ Wk,
                            const float* __restrict__ Wv) {
    const int which = blockIdx.z;
    const float* W = (which == 0) ? Wq : ((which == 1) ? Wk : Wv);
    __half* outbuf = (which == 0) ? g_Q : ((which == 1) ? g_K : g_V);

    __shared__ __half sA[BM][BK + 8];
    __shared__ __half sB[BK][BN + 8];
    __shared__ float stage[8][16][20];

    const int m0 = blockIdx.y * BM;
    const int n0 = blockIdx.x * BN;
    const int tid = threadIdx.x;
    const int wid = tid >> 5;
    const int lane = tid & 31;
    const int wr = wid >> 2;
    const int wc = wid & 3;

    wmma::fragment<wmma::accumulator, 16, 16, 16, float> acc[4][2];
#pragma unroll
    for (int i = 0; i < 4; i++) {
#pragma unroll
        for (int j = 0; j < 2; j++) {
            wmma::fill_fragment(acc[i][j], 0.0f);
        }
    }

    for (int k0 = 0; k0 < DIN; k0 += BK) {
#pragma unroll
        for (int it = 0; it < 4; it++) {
            int u = tid + it * NTHREADS;
            int r = u >> 3;
            int g = u & 7;
            float4 v = *(const float4*)&x[(size_t)(m0 + r) * DIN + k0 + g * 4];
            *(__half2*)&sA[r][g * 4]     = __floats2half2_rn(v.x, v.y);
            *(__half2*)&sA[r][g * 4 + 2] = __floats2half2_rn(v.z, v.w);
        }
#pragma unroll
        for (int it = 0; it < 4; it++) {
            int u = tid + it * NTHREADS;
            int r = u >> 5;
            int g = u & 31;
            float4 v = *(const float4*)&W[(size_t)(k0 + r) * DOUT + n0 + g * 4];
            *(__half2*)&sB[r][g * 4]     = __floats2half2_rn(v.x, v.y);
            *(__half2*)&sB[r][g * 4 + 2] = __floats2half2_rn(v.z, v.w);
        }
        __syncthreads();

#pragma unroll
        for (int kk = 0; kk < BK; kk += 16) {
            wmma::fragment<wmma::matrix_a, 16, 16, 16, __half, wmma::row_major> af[4];
            wmma::fragment<wmma::matrix_b, 16, 16, 16, __half, wmma::row_major> bf[2];
#pragma unroll
            for (int i = 0; i < 4; i++) {
                wmma::load_matrix_sync(af[i], &sA[wr * 64 + i * 16][kk], BK + 8);
            }
#pragma unroll
            for (int j = 0; j < 2; j++) {
                wmma::load_matrix_sync(bf[j], &sB[kk][wc * 32 + j * 16], BN + 8);
            }
#pragma unroll
            for (int i = 0; i < 4; i++) {
#pragma unroll
                for (int j = 0; j < 2; j++) {
                    wmma::mma_sync(acc[i][j], af[i], bf[j], acc[i][j]);
                }
            }
        }
        __syncthreads();
    }

#pragma unroll
    for (int i = 0; i < 4; i++) {
#pragma unroll
        for (int j = 0; j < 2; j++) {
            wmma::store_matrix_sync(&stage[wid][0][0], acc[i][j], 20, wmma::mem_row_major);
            __syncwarp();
#pragma unroll
            for (int q = 0; q < 8; q++) {
                int e = lane * 8 + q;
                int r = e >> 4;
                int c = e & 15;
                size_t go = (size_t)(m0 + wr * 64 + i * 16 + r) * DOUT + (n0 + wc * 32 + j * 16 + c);
                outbuf[go] = __float2half(stage[wid][r][c]);
            }
            __syncwarp();
        }
    }
}

// ---------------------------------------------------------------------------
// Kernel 2: scores  S[b,m,n] = sum_d Q[b,m,d] * K[b,n,d]  (fp32 out)
// BK2=64, register-prefetch double buffering.
// ---------------------------------------------------------------------------
__global__ void __launch_bounds__(NTHREADS, 2) scores_kernel() {
    const int b = blockIdx.z;
    const __half* Qb = g_Q + (size_t)b * SEQ * DOUT;
    const __half* Kb = g_K + (size_t)b * SEQ * DOUT;
    float* Sb = g_S + (size_t)b * SEQ * SEQ;

    __shared__ __half sA[BM][BK2 + 8];   // Q tile [m][k]
    __shared__ __half sB[BN][BK2 + 8];   // K tile [n][k]

    const int m0 = blockIdx.y * BM;
    const int n0 = blockIdx.x * BN;
    const int tid = threadIdx.x;
    const int wid = tid >> 5;
    const int wr = wid >> 2;
    const int wc = wid & 3;

    // per-thread load coords: 1024 uint4 per tile, 4 per thread
    const int lr = tid >> 1;             // row pair base: 2 threads per row... no:
    // u = tid + it*256; r = u >> 3 (8 uint4 per 64-half row); g = u & 7

    wmma::fragment<wmma::accumulator, 16, 16, 16, float> acc[4][2];
#pragma unroll
    for (int i = 0; i < 4; i++) {
#pragma unroll
        for (int j = 0; j < 2; j++) {
            wmma::fill_fragment(acc[i][j], 0.0f);
        }
    }

    // iteration 0: load directly to smem
#pragma unroll
    for (int it = 0; it < 4; it++) {
        int u = tid + it * NTHREADS;
        int r = u >> 3;
        int g = u & 7;
        *(uint4*)&sA[r][g * 8] = *(const uint4*)&Qb[(size_t)(m0 + r) * DOUT + g * 8];
        *(uint4*)&sB[r][g * 8] = *(const uint4*)&Kb[(size_t)(n0 + r) * DOUT + g * 8];
    }
    __syncthreads();

    uint4 pa[4];
    uint4 pb[4];

    for (int k0 = 0; k0 < DOUT; k0 += BK2) {
        const int kn = k0 + BK2;
        if (kn < DOUT) {
#pragma unroll
            for (int it = 0; it < 4; it++) {
                int u = tid + it * NTHREADS;
                int r = u >> 3;
                int g = u & 7;
                pa[it] = *(const uint4*)&Qb[(size_t)(m0 + r) * DOUT + kn + g * 8];
                pb[it] = *(const uint4*)&Kb[(size_t)(n0 + r) * DOUT + kn + g * 8];
            }
        }

#pragma unroll
        for (int kk = 0; kk < BK2; kk += 16) {
            wmma::fragment<wmma::matrix_a, 16, 16, 16, __half, wmma::row_major> af[4];
            wmma::fragment<wmma::matrix_b, 16, 16, 16, __half, wmma::col_major> bf[2];
#pragma unroll
            for (int i = 0; i < 4; i++) {
                wmma::load_matrix_sync(af[i], &sA[wr * 64 + i * 16][kk], BK2 + 8);
            }
#pragma unroll
            for (int j = 0; j < 2; j++) {
                wmma::load_matrix_sync(bf[j], &sB[wc * 32 + j * 16][kk], BK2 + 8);
            }
#pragma unroll
            for (int i = 0; i < 4; i++) {
#pragma unroll
                for (int j = 0; j < 2; j++) {
                    wmma::mma_sync(acc[i][j], af[i], bf[j], acc[i][j]);
                }
            }
        }
        __syncthreads();

        if (kn < DOUT) {
#pragma unroll
            for (int it = 0; it < 4; it++) {
                int u = tid + it * NTHREADS;
                int r = u >> 3;
                int g = u & 7;
                *(uint4*)&sA[r][g * 8] = pa[it];
                *(uint4*)&sB[r][g * 8] = pb[it];
            }
            __syncthreads();
        }
    }

#pragma unroll
    for (int i = 0; i < 4; i++) {
#pragma unroll
        for (int j = 0; j < 2; j++) {
            wmma::store_matrix_sync(&Sb[(size_t)(m0 + wr * 64 + i * 16) * SEQ + n0 + wc * 32 + j * 16],
                                    acc[i][j], SEQ, wmma::mem_row_major);
        }
    }
}

// ---------------------------------------------------------------------------
// Kernel 3: row softmax with scale, fp32 in -> fp16 out.  One block per row.
// ---------------------------------------------------------------------------
__global__ void softmax_kernel() {
    const size_t row = blockIdx.x;
    const float* s = g_S + row * SEQ;
    __half* p = g_P + row * SEQ;
    const int tid = threadIdx.x;
    const int wid = tid >> 5;
    const int lane = tid & 31;

    __shared__ float red[8];

    float4 v[4];
    float m = -1e30f;
#pragma unroll
    for (int i = 0; i < 4; i++) {
        v[i] = ((const float4*)s)[i * 256 + tid];
        m = fmaxf(m, fmaxf(fmaxf(v[i].x, v[i].y), fmaxf(v[i].z, v[i].w)));
    }
#pragma unroll
    for (int o = 16; o > 0; o >>= 1) {
        m = fmaxf(m, __shfl_xor_sync(0xffffffffu, m, o));
    }
    if (lane == 0) {
        red[wid] = m;
    }
    __syncthreads();
    float rowmax = red[0];
#pragma unroll
    for (int k = 1; k < 8; k++) {
        rowmax = fmaxf(rowmax, red[k]);
    }
    __syncthreads();

    float e[16];
    float sum = 0.0f;
#pragma unroll
    for (int i = 0; i < 4; i++) {
        e[i * 4 + 0] = __expf((v[i].x - rowmax) * QSCALE);
        e[i * 4 + 1] = __expf((v[i].y - rowmax) * QSCALE);
        e[i * 4 + 2] = __expf((v[i].z - rowmax) * QSCALE);
        e[i * 4 + 3] = __expf((v[i].w - rowmax) * QSCALE);
        sum += e[i * 4 + 0] + e[i * 4 + 1] + e[i * 4 + 2] + e[i * 4 + 3];
    }
#pragma unroll
    for (int o = 16; o > 0; o >>= 1) {
        sum += __shfl_xor_sync(0xffffffffu, sum, o);
    }
    if (lane == 0) {
        red[wid] = sum;
    }
    __syncthreads();
    float rowsum = 0.0f;
#pragma unroll
    for (int k = 0; k < 8; k++) {
        rowsum += red[k];
    }
    const float inv = 1.0f / rowsum;

#pragma unroll
    for (int i = 0; i < 4; i++) {
        __half2 p0 = __floats2half2_rn(e[i * 4 + 0] * inv, e[i * 4 + 1] * inv);
        __half2 p1 = __floats2half2_rn(e[i * 4 + 2] * inv, e[i * 4 + 3] * inv);
        size_t c = (size_t)(i * 256 + tid) * 4;
        *(__half2*)&p[c]     = p0;
        *(__half2*)&p[c + 2] = p1;
    }
}

// ---------------------------------------------------------------------------
// Kernel 4: output  O[b,m,d] = sum_k P[b,m,k] * V[b,k,d]  (fp32 out)
// BK2=64, register-prefetch double buffering.
// ---------------------------------------------------------------------------
__global__ void __launch_bounds__(NTHREADS, 2) out_kernel(float* __restrict__ out) {
    const int b = blockIdx.z;
    const __half* Pb = g_P + (size_t)b * SEQ * SEQ;
    const __half* Vb = g_V + (size_t)b * SEQ * DOUT;
    float* Ob = out + (size_t)b * SEQ * DOUT;

    __shared__ __half sA[BM][BK2 + 8];    // P tile [m][k]
    __shared__ __half sB[BK2][BN + 8];    // V tile [k][n]

    const int m0 = blockIdx.y * BM;
    const int n0 = blockIdx.x * BN;
    const int tid = threadIdx.x;
    const int wid = tid >> 5;
    const int wr = wid >> 2;
    const int wc = wid & 3;

    wmma::fragment<wmma::accumulator, 16, 16, 16, float> acc[4][2];
#pragma unroll
    for (int i = 0; i < 4; i++) {
#pragma unroll
        for (int j = 0; j < 2; j++) {
            wmma::fill_fragment(acc[i][j], 0.0f);
        }
    }

    // iteration 0: load directly to smem
#pragma unroll
    for (int it = 0; it < 4; it++) {
        int u = tid + it * NTHREADS;
        int ra = u >> 3;
        int ga = u & 7;
        *(uint4*)&sA[ra][ga * 8] = *(const uint4*)&Pb[(size_t)(m0 + ra) * SEQ + ga * 8];
        int rb = u >> 4;
        int gb = u & 15;
        *(uint4*)&sB[rb][gb * 8] = *(const uint4*)&Vb[(size_t)rb * DOUT + n0 + gb * 8];
    }
    __syncthreads();

    uint4 pa[4];
    uint4 pb[4];

    for (int k0 = 0; k0 < SEQ; k0 += BK2) {
        const int kn = k0 + BK2;
        if (kn < SEQ) {
#pragma unroll
            for (int it = 0; it < 4; it++) {
                int u = tid + it * NTHREADS;
                int ra = u >> 3;
                int ga = u & 7;
                pa[it] = *(const uint4*)&Pb[(size_t)(m0 + ra) * SEQ + kn + ga * 8];
                int rb = u >> 4;
                int gb = u & 15;
                pb[it] = *(const uint4*)&Vb[(size_t)(kn + rb) * DOUT + n0 + gb * 8];
            }
        }

#pragma unroll
        for (int kk = 0; kk < BK2; kk += 16) {
            wmma::fragment<wmma::matrix_a, 16, 16, 16, __half, wmma::row_major> af[4];
            wmma::fragment<wmma::matrix_b, 16, 16, 16, __half, wmma::row_major> bf[2];
#pragma unroll
            for (int i = 0; i < 4; i++) {
                wmma::load_matrix_sync(af[i], &sA[wr * 64 + i * 16][kk], BK2 + 8);
            }
#pragma unroll
            for (int j = 0; j < 2; j++) {
                wmma::load_matrix_sync(bf[j], &sB[kk][wc * 32 + j * 16], BN + 8);
            }
#pragma unroll
            for (int i = 0; i < 4; i++) {
#pragma unroll
                for (int j = 0; j < 2; j++) {
                    wmma::mma_sync(acc[i][j], af[i], bf[j], acc[i][j]);
                }
            }
        }
        __syncthreads();

        if (kn < SEQ) {
#pragma unroll
            for (int it = 0; it < 4; it++) {
                int u = tid + it * NTHREADS;
                int ra = u >> 3;
                int ga = u & 7;
                *(uint4*)&sA[ra][ga * 8] = pa[it];
                int rb = u >> 4;
                int gb = u & 15;
                *(uint4*)&sB[rb][gb * 8] = pb[it];
            }
            __syncthreads();
        }
    }

#pragma unroll
    for (int i = 0; i < 4; i++) {
#pragma unroll
        for (int j = 0; j < 2; j++) {
            wmma::store_matrix_sync(&Ob[(size_t)(m0 + wr * 64 + i * 16) * DOUT + n0 + wc * 32 + j * 16],
                                    acc[i][j], DOUT, wmma::mem_row_major);
        }
    }
}

// ---------------------------------------------------------------------------
extern "C" void kernel_launch(void* const* d_in, const int* in_sizes, int n_in,
                              void* d_out, int out_size) {
    const float* x  = (const float*)d_in[0];
    const float* Wq = (const float*)d_in[1];
    const float* Wk = (const float*)d_in[2];
    const float* Wv = (const float*)d_in[3];
    float* out = (float*)d_out;

    dim3 gproj(DOUT / BN, MTOT / BM, 3);
    proj_kernel<<<gproj, NTHREADS>>>(x, Wq, Wk, Wv);

    dim3 gsc(SEQ / BN, SEQ / BM, BATCH);
    scores_kernel<<<gsc, NTHREADS>>>();

    softmax_kernel<<<BATCH * SEQ, 256>>>();

    dim3 gout(DOUT / BN, SEQ / BM, BATCH);
    out_kernel<<<gout, NTHREADS>>>(out);
}

// round 9
// speedup vs baseline: 1.1702x; 1.0062x over previous
#include <cuda_runtime.h>
#include <cuda_fp16.h>
#include <cstdint>
#include <mma.h>

using namespace nvcuda;

// Problem dims
#define BATCH   2
#define SEQ     4096
#define DIN     512
#define DOUT    512
#define MTOT    (BATCH * SEQ)
#define QSCALE  0.04419417382415922f   // 1/sqrt(512)

// Projection GEMM tiling
#define BM 128
#define BN 128
#define BK 32
#define NTHREADS 256

// Flash attention config
#define FBM 64
#define FBN 64
#define FD  512
#define FDC 128
#define NBLK (SEQ / FBN)
#define FTHREADS 256

// smem layout (bytes)
#define SQ_STRIDE  520
#define SKV_STRIDE 136
#define SP_STRIDE  72
#define SQ_OFF   0
#define SQ_BYTES (64 * SQ_STRIDE * 2)
#define SKV_OFF  SQ_BYTES
#define SKV_BUF_BYTES (64 * SKV_STRIDE * 2)
#define SP_OFF   (SKV_OFF + 4 * SKV_BUF_BYTES)
#define SP_BYTES (64 * SP_STRIDE * 2)
#define MRUN_OFF (SP_OFF + SP_BYTES)
#define LRUN_OFF (MRUN_OFF + 256)
#define WMAX_OFF (LRUN_OFF + 256)
#define WSUM_OFF (WMAX_OFF + 512)
#define SMEM_TOTAL (WSUM_OFF + 512)

// Scratch (device globals)
__device__ __align__(128) __half g_Q[(size_t)MTOT * DOUT];
__device__ __align__(128) __half g_K[(size_t)MTOT * DOUT];
__device__ __align__(128) __half g_V[(size_t)MTOT * DOUT];

// ---------------------------------------------------------------------------
// PTX helpers
// ---------------------------------------------------------------------------
__device__ __forceinline__ uint32_t smem_u32(const void* p) {
    return (uint32_t)__cvta_generic_to_shared(p);
}

__device__ __forceinline__ void cp_async16(uint32_t dst, const void* src) {
    asm volatile("cp.async.cg.shared.global [%0], [%1], 16;" :: "r"(dst), "l"(src));
}

__device__ __forceinline__ void cp_commit() {
    asm volatile("cp.async.commit_group;");
}

__device__ __forceinline__ void cp_wait1() {
    asm volatile("cp.async.wait_group 1;");
}

__device__ __forceinline__ void ldm_x4(uint32_t& a0, uint32_t& a1, uint32_t& a2, uint32_t& a3,
                                       uint32_t addr) {
    asm volatile("ldmatrix.sync.aligned.m8n8.x4.shared.b16 {%0,%1,%2,%3}, [%4];"
                 : "=r"(a0), "=r"(a1), "=r"(a2), "=r"(a3) : "r"(addr));
}

__device__ __forceinline__ void ldm_x4_t(uint32_t& a0, uint32_t& a1, uint32_t& a2, uint32_t& a3,
                                         uint32_t addr) {
    asm volatile("ldmatrix.sync.aligned.m8n8.x4.trans.shared.b16 {%0,%1,%2,%3}, [%4];"
                 : "=r"(a0), "=r"(a1), "=r"(a2), "=r"(a3) : "r"(addr));
}

__device__ __forceinline__ void mma16816(float* d, uint32_t a0, uint32_t a1, uint32_t a2,
                                         uint32_t a3, uint32_t b0, uint32_t b1) {
    asm volatile("mma.sync.aligned.m16n8k16.row.col.f32.f16.f16.f32 "
                 "{%0,%1,%2,%3}, {%4,%5,%6,%7}, {%8,%9}, {%0,%1,%2,%3};"
                 : "+f"(d[0]), "+f"(d[1]), "+f"(d[2]), "+f"(d[3])
                 : "r"(a0), "r"(a1), "r"(a2), "r"(a3), "r"(b0), "r"(b1));
}

// K/V chunk loader. ch 0..3 = K d-chunks, 4..7 = V d-chunks; buffer = ch&3.
__device__ __forceinline__ void load_chunk(char* sm, const __half* Kb, const __half* Vb,
                                           int tid, int j, int ch) {
    const __half* src = (ch < 4) ? Kb : Vb;
    const int d0 = (ch & 3) * FDC;
    __half* dbuf = (__half*)(sm + SKV_OFF + (size_t)(ch & 3) * SKV_BUF_BYTES);
    const int n0 = j * FBN;
#pragma unroll
    for (int it = 0; it < 4; it++) {
        int idx = tid + it * FTHREADS;
        int r = idx >> 4;
        int c8 = idx & 15;
        cp_async16(smem_u32(&dbuf[r * SKV_STRIDE + c8 * 8]),
                   &src[(size_t)(n0 + r) * FD + d0 + c8 * 8]);
    }
}

// ---------------------------------------------------------------------------
// Kernel 1: fused projections (fp16 out; Q pre-scaled by QSCALE)
// ---------------------------------------------------------------------------
__global__ void proj_kernel(const float* __restrict__ x,
                            const float* __restrict__ Wq,
                            const float* __restrict__ Wk,
                            const float* __restrict__ Wv) {
    const int which = blockIdx.z;
    const float* W = (which == 0) ? Wq : ((which == 1) ? Wk : Wv);
    __half* outbuf = (which == 0) ? g_Q : ((which == 1) ? g_K : g_V);
    const float oscale = (which == 0) ? QSCALE : 1.0f;

    __shared__ __half sA[BM][BK + 8];
    __shared__ __half sB[BK][BN + 8];
    __shared__ float stage[8][16][20];

    const int m0 = blockIdx.y * BM;
    const int n0 = blockIdx.x * BN;
    const int tid = threadIdx.x;
    const int wid = tid >> 5;
    const int lane = tid & 31;
    const int wr = wid >> 2;
    const int wc = wid & 3;

    wmma::fragment<wmma::accumulator, 16, 16, 16, float> acc[4][2];
#pragma unroll
    for (int i = 0; i < 4; i++) {
#pragma unroll
        for (int j = 0; j < 2; j++) {
            wmma::fill_fragment(acc[i][j], 0.0f);
        }
    }

    for (int k0 = 0; k0 < DIN; k0 += BK) {
#pragma unroll
        for (int it = 0; it < 4; it++) {
            int u = tid + it * NTHREADS;
            int r = u >> 3;
            int g = u & 7;
            float4 v = *(const float4*)&x[(size_t)(m0 + r) * DIN + k0 + g * 4];
            *(__half2*)&sA[r][g * 4]     = __floats2half2_rn(v.x, v.y);
            *(__half2*)&sA[r][g * 4 + 2] = __floats2half2_rn(v.z, v.w);
        }
#pragma unroll
        for (int it = 0; it < 4; it++) {
            int u = tid + it * NTHREADS;
            int r = u >> 5;
            int g = u & 31;
            float4 v = *(const float4*)&W[(size_t)(k0 + r) * DOUT + n0 + g * 4];
            *(__half2*)&sB[r][g * 4]     = __floats2half2_rn(v.x, v.y);
            *(__half2*)&sB[r][g * 4 + 2] = __floats2half2_rn(v.z, v.w);
        }
        __syncthreads();

#pragma unroll
        for (int kk = 0; kk < BK; kk += 16) {
            wmma::fragment<wmma::matrix_a, 16, 16, 16, __half, wmma::row_major> af[4];
            wmma::fragment<wmma::matrix_b, 16, 16, 16, __half, wmma::row_major> bf[2];
#pragma unroll
            for (int i = 0; i < 4; i++) {
                wmma::load_matrix_sync(af[i], &sA[wr * 64 + i * 16][kk], BK + 8);
            }
#pragma unroll
            for (int j = 0; j < 2; j++) {
                wmma::load_matrix_sync(bf[j], &sB[kk][wc * 32 + j * 16], BN + 8);
            }
#pragma unroll
            for (int i = 0; i < 4; i++) {
#pragma unroll
                for (int j = 0; j < 2; j++) {
                    wmma::mma_sync(acc[i][j], af[i], bf[j], acc[i][j]);
                }
            }
        }
        __syncthreads();
    }

#pragma unroll
    for (int i = 0; i < 4; i++) {
#pragma unroll
        for (int j = 0; j < 2; j++) {
            wmma::store_matrix_sync(&stage[wid][0][0], acc[i][j], 20, wmma::mem_row_major);
            __syncwarp();
#pragma unroll
            for (int q = 0; q < 8; q++) {
                int e = lane * 8 + q;
                int r = e >> 4;
                int c = e & 15;
                size_t go = (size_t)(m0 + wr * 64 + i * 16 + r) * DOUT + (n0 + wc * 32 + j * 16 + c);
                outbuf[go] = __float2half(stage[wid][r][c] * oscale);
            }
            __syncwarp();
        }
    }
}

// ---------------------------------------------------------------------------
// Kernel 2: fused flash attention.  O = softmax(Q K^T) V, fp32 out.
// Grid (SEQ/FBM, BATCH), 8 warps: rg = wid>>1 (16-row slab), cg = wid&1.
// ---------------------------------------------------------------------------
__global__ void __launch_bounds__(FTHREADS, 1)
flash_kernel(float* __restrict__ out) {
    extern __shared__ char smem[];
    __half* sQ  = (__half*)(smem + SQ_OFF);
    __half* sP  = (__half*)(smem + SP_OFF);
    float* mrun = (float*)(smem + MRUN_OFF);
    float* lrun = (float*)(smem + LRUN_OFF);
    float* wmax = (float*)(smem + WMAX_OFF);
    float* wsum = (float*)(smem + WSUM_OFF);

    const int b = blockIdx.y;
    const int m_base = blockIdx.x * FBM;
    const int tid = threadIdx.x;
    const int wid = tid >> 5;
    const int lane = tid & 31;
    const int rg = wid >> 1;
    const int cg = wid & 1;

    const __half* Qb = g_Q + (size_t)b * SEQ * FD;
    const __half* Kb = g_K + (size_t)b * SEQ * FD;
    const __half* Vb = g_V + (size_t)b * SEQ * FD;

    if (tid < 64) {
        mrun[tid] = -1e30f;
        lrun[tid] = 0.0f;
    }

    // Load Q tile (one cp.async group)
#pragma unroll
    for (int it = 0; it < 16; it++) {
        int idx = tid + it * FTHREADS;
        int r = idx >> 6;
        int c8 = idx & 63;
        cp_async16(smem_u32(&sQ[r * SQ_STRIDE + c8 * 8]),
                   &Qb[(size_t)(m_base + r) * FD + c8 * 8]);
    }
    cp_commit();

    load_chunk(smem, Kb, Vb, tid, 0, 0);
    cp_commit();
    load_chunk(smem, Kb, Vb, tid, 0, 1);
    cp_commit();

    float o[32][4];
#pragma unroll
    for (int i = 0; i < 32; i++) {
#pragma unroll
        for (int e = 0; e < 4; e++) {
            o[i][e] = 0.0f;
        }
    }

    const int r0 = rg * 16 + (lane >> 2);
    const int r1 = r0 + 8;

    for (int j = 0; j < NBLK; j++) {
        float s[4][4];
#pragma unroll
        for (int t = 0; t < 4; t++) {
#pragma unroll
            for (int e = 0; e < 4; e++) {
                s[t][e] = 0.0f;
            }
        }

#pragma unroll
        for (int cc = 0; cc < 8; cc++) {
            cp_wait1();
            __syncthreads();

            int pj = j;
            int pc = cc + 2;
            if (pc >= 8) {
                pj = j + 1;
                pc = pc - 8;
            }
            if (pj < NBLK) {
                load_chunk(smem, Kb, Vb, tid, pj, pc);
            }
            cp_commit();

            const __half* buf = (const __half*)(smem + SKV_OFF + (size_t)(cc & 3) * SKV_BUF_BYTES);

            if (cc < 4) {
                // ---- S += Q[:, chunk] * K[:, chunk]^T ----
#pragma unroll
                for (int ks = 0; ks < 8; ks++) {
                    uint32_t a0, a1, a2, a3;
                    int arow = rg * 16 + (lane & 15);
                    int acol = cc * 128 + ks * 16 + ((lane & 16) >> 1);
                    ldm_x4(a0, a1, a2, a3, smem_u32(&sQ[arow * SQ_STRIDE + acol]));
#pragma unroll
                    for (int nt2 = 0; nt2 < 2; nt2++) {
                        uint32_t b0, b1, b2, b3;
                        int brow = cg * 32 + nt2 * 16 + (lane & 7) + ((lane & 16) >> 1);
                        int bcol = ks * 16 + (lane & 8);
                        ldm_x4(b0, b1, b2, b3, smem_u32(&buf[brow * SKV_STRIDE + bcol]));
                        mma16816(s[2 * nt2],     a0, a1, a2, a3, b0, b1);
                        mma16816(s[2 * nt2 + 1], a0, a1, a2, a3, b2, b3);
                    }
                }
                if (cc == 3) {
                    // ---- online softmax ----
                    float mx0 = -1e30f;
                    float mx1 = -1e30f;
#pragma unroll
                    for (int t = 0; t < 4; t++) {
                        mx0 = fmaxf(mx0, fmaxf(s[t][0], s[t][1]));
                        mx1 = fmaxf(mx1, fmaxf(s[t][2], s[t][3]));
                    }
                    mx0 = fmaxf(mx0, __shfl_xor_sync(0xffffffffu, mx0, 1));
                    mx0 = fmaxf(mx0, __shfl_xor_sync(0xffffffffu, mx0, 2));
                    mx1 = fmaxf(mx1, __shfl_xor_sync(0xffffffffu, mx1, 1));
                    mx1 = fmaxf(mx1, __shfl_xor_sync(0xffffffffu, mx1, 2));
                    if ((lane & 3) == 0) {
                        wmax[cg * 64 + r0] = mx0;
                        wmax[cg * 64 + r1] = mx1;
                    }
                    __syncthreads();
                    float mo0 = mrun[r0];
                    float mo1 = mrun[r1];
                    float mn0 = fmaxf(mo0, fmaxf(wmax[r0], wmax[64 + r0]));
                    float mn1 = fmaxf(mo1, fmaxf(wmax[r1], wmax[64 + r1]));
                    float al0 = __expf(mo0 - mn0);
                    float al1 = __expf(mo1 - mn1);
                    float sum0 = 0.0f;
                    float sum1 = 0.0f;
#pragma unroll
                    for (int t = 0; t < 4; t++) {
                        float p00 = __expf(s[t][0] - mn0);
                        float p01 = __expf(s[t][1] - mn0);
                        float p10 = __expf(s[t][2] - mn1);
                        float p11 = __expf(s[t][3] - mn1);
                        sum0 += p00 + p01;
                        sum1 += p10 + p11;
                        int col = cg * 32 + t * 8 + 2 * (lane & 3);
                        *(__half2*)&sP[r0 * SP_STRIDE + col] = __floats2half2_rn(p00, p01);
                        *(__half2*)&sP[r1 * SP_STRIDE + col] = __floats2half2_rn(p10, p11);
                    }
#pragma unroll
                    for (int i = 0; i < 32; i++) {
                        o[i][0] *= al0;
                        o[i][1] *= al0;
                        o[i][2] *= al1;
                        o[i][3] *= al1;
                    }
                    sum0 += __shfl_xor_sync(0xffffffffu, sum0, 1);
                    sum0 += __shfl_xor_sync(0xffffffffu, sum0, 2);
                    sum1 += __shfl_xor_sync(0xffffffffu, sum1, 1);
                    sum1 += __shfl_xor_sync(0xffffffffu, sum1, 2);
                    if ((lane & 3) == 0) {
                        wsum[cg * 64 + r0] = sum0;
                        wsum[cg * 64 + r1] = sum1;
                    }
                    __syncthreads();
                    if (cg == 0 && (lane & 3) == 0) {
                        lrun[r0] = lrun[r0] * al0 + wsum[r0] + wsum[64 + r0];
                        lrun[r1] = lrun[r1] * al1 + wsum[r1] + wsum[64 + r1];
                        mrun[r0] = mn0;
                        mrun[r1] = mn1;
                    }
                }
            } else {
                // ---- O[:, chunk] += P * V[:, chunk] ----
                const int c2 = cc - 4;
#pragma unroll
                for (int ks = 0; ks < 4; ks++) {
                    uint32_t a0, a1, a2, a3;
                    int arow = rg * 16 + (lane & 15);
                    int acol = ks * 16 + ((lane & 16) >> 1);
                    ldm_x4(a0, a1, a2, a3, smem_u32(&sP[arow * SP_STRIDE + acol]));
#pragma unroll
                    for (int nt2 = 0; nt2 < 4; nt2++) {
                        uint32_t b0, b1, b2, b3;
                        int brow = ks * 16 + (lane & 15);
                        int bcol = cg * 64 + nt2 * 16 + ((lane & 16) >> 1);
                        ldm_x4_t(b0, b1, b2, b3, smem_u32(&buf[brow * SKV_STRIDE + bcol]));
                        int t = c2 * 8 + nt2 * 2;
                        mma16816(o[t],     a0, a1, a2, a3, b0, b1);
                        mma16816(o[t + 1], a0, a1, a2, a3, b2, b3);
                    }
                }
            }
        }
    }

    // ---- epilogue: O /= l, store fp32 ----
    __syncthreads();
    float inv0 = 1.0f / lrun[r0];
    float inv1 = 1.0f / lrun[r1];
    float* Ob = out + ((size_t)b * SEQ + m_base) * FD;
#pragma unroll
    for (int c2 = 0; c2 < 4; c2++) {
#pragma unroll
        for (int nt = 0; nt < 8; nt++) {
            int t = c2 * 8 + nt;
            int col = c2 * 128 + cg * 64 + nt * 8 + 2 * (lane & 3);
            *(float2*)&Ob[(size_t)r0 * FD + col] = make_float2(o[t][0] * inv0, o[t][1] * inv0);
            *(float2*)&Ob[(size_t)r1 * FD + col] = make_float2(o[t][2] * inv1, o[t][3] * inv1);
        }
    }
}

// ---------------------------------------------------------------------------
extern "C" void kernel_launch(void* const* d_in, const int* in_sizes, int n_in,
                              void* d_out, int out_size) {
    const float* x  = (const float*)d_in[0];
    const float* Wq = (const float*)d_in[1];
    const float* Wk = (const float*)d_in[2];
    const float* Wv = (const float*)d_in[3];
    float* out = (float*)d_out;

    cudaFuncSetAttribute(flash_kernel, cudaFuncAttributeMaxDynamicSharedMemorySize, SMEM_TOTAL);

    dim3 gproj(DOUT / BN, MTOT / BM, 3);
    proj_kernel<<<gproj, NTHREADS>>>(x, Wq, Wk, Wv);

    dim3 gflash(SEQ / FBM, BATCH);
    flash_kernel<<<gflash, FTHREADS, SMEM_TOTAL>>>(out);
}